// round 5
// baseline (speedup 1.0000x reference)
#include <cuda_runtime.h>
#include <cuda_fp16.h>
#include <cstdint>

// out[i] = x[i] + sum_j adj[i,j]*x[j],  N=16384, D=128, adj int32 in {0,1}.
//
// Legacy-PTX path (compute_103 has no tcgen05): fp16 mma.sync.m16n8k16 with
// f32 accumulators. adj low bytes are the value (upper bytes always 0), so
// PRMT+IMAD packs two int32 -> fp16x2 {0.0,1.0}. x is pre-transposed/converted
// to fp16 xT[d][j] once (4MB, L2-resident) and serves as the col-major B.

#define NROWS  16384
#define DCOLS  128
#define TILE_M 128
#define TILE_K 64
#define CHUNKS (NROWS / TILE_K)          // 256
#define SMEM_DYN (1024 + 4 * 16384)      // pad + A0,A1,B0,B1 (16KB each)

__device__ __align__(16) __half g_xT[(size_t)DCOLS * NROWS];   // [d][j], 4 MB

// ---------------------------------------------------------------- helpers
__device__ __forceinline__ uint32_t smem_u32(const void* p) {
    uint32_t a;
    asm("{ .reg .u64 t; cvta.to.shared.u64 t, %1; cvt.u32.u64 %0, t; }" : "=r"(a) : "l"(p));
    return a;
}
__device__ __forceinline__ uint32_t sw128(uint32_t o) { return o ^ ((o >> 3) & 0x70u); }

__device__ __forceinline__ void sts64(uint32_t a, uint32_t v0, uint32_t v1) {
    asm volatile("st.shared.v2.b32 [%0], {%1,%2};" :: "r"(a), "r"(v0), "r"(v1) : "memory");
}
__device__ __forceinline__ void cp_async16(uint32_t saddr, const void* gptr) {
    asm volatile("cp.async.cg.shared.global [%0], [%1], 16;"
                 :: "r"(saddr), "l"(__cvta_generic_to_global(gptr)) : "memory");
}
__device__ __forceinline__ void cp_commit() {
    asm volatile("cp.async.commit_group;" ::: "memory");
}
__device__ __forceinline__ void cp_wait0() {
    asm volatile("cp.async.wait_group 0;" ::: "memory");
}
__device__ __forceinline__ void cp_wait1() {
    asm volatile("cp.async.wait_group 1;" ::: "memory");
}
__device__ __forceinline__ void ldmx4(uint32_t* r, uint32_t addr) {
    asm volatile("ldmatrix.sync.aligned.m8n8.x4.shared.b16 {%0,%1,%2,%3}, [%4];"
                 : "=r"(r[0]), "=r"(r[1]), "=r"(r[2]), "=r"(r[3]) : "r"(addr));
}
__device__ __forceinline__ void mma16816(float* d, const uint32_t* a, uint32_t b0, uint32_t b1) {
    asm volatile("mma.sync.aligned.m16n8k16.row.col.f32.f16.f16.f32 "
                 "{%0,%1,%2,%3}, {%4,%5,%6,%7}, {%8,%9}, {%0,%1,%2,%3};"
                 : "+f"(d[0]), "+f"(d[1]), "+f"(d[2]), "+f"(d[3])
                 : "r"(a[0]), "r"(a[1]), "r"(a[2]), "r"(a[3]), "r"(b0), "r"(b1));
}

// ---------------------------------------------------------------- prep: x -> fp16 transposed [d][j]
__global__ void prep_xT_kernel(const float* __restrict__ x) {
    __shared__ float tile[32][33];
    const int j0 = blockIdx.x * 32;
    const int d0 = blockIdx.y * 32;
    const int tx = threadIdx.x, ty = threadIdx.y;   // 32 x 8
#pragma unroll
    for (int k = 0; k < 32; k += 8)
        tile[ty + k][tx] = x[(size_t)(j0 + ty + k) * DCOLS + d0 + tx];
    __syncthreads();
#pragma unroll
    for (int k = 0; k < 32; k += 8)
        g_xT[(size_t)(d0 + ty + k) * NROWS + j0 + tx] = __float2half_rn(tile[tx][ty + k]);
}

// ---------------------------------------------------------------- main GEMM
__global__ void __launch_bounds__(256, 1) adjmm_kernel(
    const float* __restrict__ x, const int* __restrict__ adj, float* __restrict__ out)
{
    extern __shared__ char smraw[];
    char* sm = (char*)((((uintptr_t)smraw) + 1023) & ~(uintptr_t)1023);
    const uint32_t sb = smem_u32(sm);
    const uint32_t A_BUF[2] = { sb,           sb + 16384 };
    const uint32_t B_BUF[2] = { sb + 32768,   sb + 49152 };

    const int tid  = threadIdx.x;
    const int w    = tid >> 5;
    const int lane = tid & 31;
    const int wr   = w >> 1;          // warp row (0..3) -> m offset 32*wr
    const int wc   = w & 1;           // warp col (0..1) -> n offset 64*wc
    const int m0g  = blockIdx.x * TILE_M;

    // ---- staged A registers (raw int32 0/1, converted at STS time)
    int4 ra[8];

    auto ldgA = [&](int c) {
#pragma unroll
        for (int i = 0; i < 8; ++i) {
            int idx = i * 256 + tid;            // 0..2047 -> 128 rows x 16 int4
            int row = idx >> 4, q = idx & 15;
            ra[i] = *(const int4*)(adj + (size_t)(m0g + row) * NROWS + c * TILE_K + q * 4);
        }
    };
    auto stsA = [&](uint32_t base) {
#pragma unroll
        for (int i = 0; i < 8; ++i) {
            int idx = i * 256 + tid;
            int row = idx >> 4, q = idx & 15;
            uint32_t p01 = __byte_perm((uint32_t)ra[i].x, (uint32_t)ra[i].y, 0x5410) * 0x3C00u;
            uint32_t p23 = __byte_perm((uint32_t)ra[i].z, (uint32_t)ra[i].w, 0x5410) * 0x3C00u;
            sts64(base + sw128((uint32_t)(row * 128 + q * 8)), p01, p23);
        }
    };
    auto cpB = [&](int c, uint32_t base) {
#pragma unroll
        for (int i = 0; i < 4; ++i) {
            int idx = i * 256 + tid;            // 0..1023 -> 128 rows x 8 segs
            int row = idx >> 3, seg = idx & 7;
            cp_async16(base + sw128((uint32_t)(row * 128 + seg * 16)),
                       g_xT + (size_t)row * NROWS + c * TILE_K + seg * 8);
        }
        cp_commit();
    };

    float acc[2][8][4];
#pragma unroll
    for (int mf = 0; mf < 2; ++mf)
#pragma unroll
        for (int nf = 0; nf < 8; ++nf)
#pragma unroll
            for (int i = 0; i < 4; ++i) acc[mf][nf][i] = 0.0f;

    // ---- prologue
    ldgA(0);
    stsA(A_BUF[0]);
    ldgA(1);
    cpB(0, B_BUF[0]);
    cpB(1, B_BUF[1]);
    cp_wait1();           // B0 landed
    __syncthreads();      // A0 + B0 visible

    // ---- main loop: compute(c) | STS A(c+1) | LDG A(c+2) | cp.async B(c+2)
    for (int c = 0; c < CHUNKS; ++c) {
        const int s = c & 1;
        const uint32_t Ab = A_BUF[s], Bb = B_BUF[s];

        // A fragments for the whole chunk: 2 m-frags x 4 k-steps
        uint32_t af[2][4][4];
#pragma unroll
        for (int mf = 0; mf < 2; ++mf)
#pragma unroll
            for (int ks = 0; ks < 4; ++ks) {
                uint32_t row = (uint32_t)(wr * 32 + mf * 16 + (lane & 15));
                uint32_t off = sw128(row * 128 + ks * 32 + ((lane >> 4) << 4));
                ldmx4(af[mf][ks], Ab + off);
            }

#pragma unroll
        for (int nf = 0; nf < 8; ++nf) {
#pragma unroll
            for (int h = 0; h < 2; ++h) {       // k half-chunks of 32
                uint32_t bf[4];
                uint32_t row = (uint32_t)(wc * 64 + nf * 8 + (lane & 7));
                uint32_t off = sw128(row * 128 + h * 64 + ((lane >> 3) << 4));
                ldmx4(bf, Bb + off);
#pragma unroll
                for (int ksl = 0; ksl < 2; ++ksl) {
                    const int ks = h * 2 + ksl;
                    mma16816(acc[0][nf], af[0][ks], bf[2 * ksl], bf[2 * ksl + 1]);
                    mma16816(acc[1][nf], af[1][ks], bf[2 * ksl], bf[2 * ksl + 1]);
                }
            }
        }

        if (c + 1 < CHUNKS) stsA(A_BUF[s ^ 1]);     // A(c+1), regs loaded last iter
        if (c + 2 < CHUNKS) ldgA(c + 2);            // prefetch into regs
        cp_wait0();                                 // B(c+1) landed
        __syncthreads();                            // everyone done with buf s
        if (c + 2 < CHUNKS) cpB(c + 2, B_BUF[s]);   // refill freed buffer
    }

    // ---- epilogue: out = x + acc
#pragma unroll
    for (int mf = 0; mf < 2; ++mf) {
#pragma unroll
        for (int nf = 0; nf < 8; ++nf) {
            const int m = m0g + wr * 32 + mf * 16 + (lane >> 2);
            const int n = wc * 64 + nf * 8 + (lane & 3) * 2;
            float2 xv0 = *(const float2*)(x + (size_t)m * DCOLS + n);
            float2 o0  = { acc[mf][nf][0] + xv0.x, acc[mf][nf][1] + xv0.y };
            *(float2*)(out + (size_t)m * DCOLS + n) = o0;
            float2 xv1 = *(const float2*)(x + (size_t)(m + 8) * DCOLS + n);
            float2 o1  = { acc[mf][nf][2] + xv1.x, acc[mf][nf][3] + xv1.y };
            *(float2*)(out + (size_t)(m + 8) * DCOLS + n) = o1;
        }
    }
}

// ---------------------------------------------------------------- launcher
extern "C" void kernel_launch(void* const* d_in, const int* in_sizes, int n_in,
                              void* d_out, int out_size) {
    const float* x   = (const float*)d_in[0];
    const int*   adj = (const int*)d_in[1];
    float*       out = (float*)d_out;
    (void)in_sizes; (void)n_in; (void)out_size;

    prep_xT_kernel<<<dim3(NROWS / 32, DCOLS / 32), dim3(32, 8)>>>(x);

    cudaFuncSetAttribute(adjmm_kernel, cudaFuncAttributeMaxDynamicSharedMemorySize, SMEM_DYN);
    adjmm_kernel<<<NROWS / TILE_M, 256, SMEM_DYN>>>(x, adj, out);
}

// round 7
// speedup vs baseline: 1.0003x; 1.0003x over previous
#include <cuda_runtime.h>
#include <cuda_fp16.h>
#include <cstdint>

// out[i] = x[i] + sum_j adj[i,j]*x[j],  N=16384, D=128, adj int32 in {0,1}.
//
// Legacy-PTX path (compute_103 has no tcgen05): fp16 mma.sync.m16n8k16 with
// f32 accumulators. adj low bytes are the value (upper bytes always 0), so
// PRMT+IMAD packs two int32 -> fp16x2 {0.0,1.0}. x is pre-transposed/converted
// to fp16 xT[d][j] once (4MB, L2-resident) and serves as the col-major B.

#define NROWS  16384
#define DCOLS  128
#define TILE_M 128
#define TILE_K 64
#define CHUNKS (NROWS / TILE_K)          // 256
#define SMEM_DYN (1024 + 4 * 16384)      // pad + A0,A1,B0,B1 (16KB each)

__device__ __align__(16) __half g_xT[(size_t)DCOLS * NROWS];   // [d][j], 4 MB

// ---------------------------------------------------------------- helpers
__device__ __forceinline__ uint32_t smem_u32(const void* p) {
    uint32_t a;
    asm("{ .reg .u64 t; cvta.to.shared.u64 t, %1; cvt.u32.u64 %0, t; }" : "=r"(a) : "l"(p));
    return a;
}
__device__ __forceinline__ uint32_t sw128(uint32_t o) { return o ^ ((o >> 3) & 0x70u); }

__device__ __forceinline__ void sts64(uint32_t a, uint32_t v0, uint32_t v1) {
    asm volatile("st.shared.v2.b32 [%0], {%1,%2};" :: "r"(a), "r"(v0), "r"(v1) : "memory");
}
__device__ __forceinline__ void cp_async16(uint32_t saddr, const void* gptr) {
    asm volatile("cp.async.cg.shared.global [%0], [%1], 16;"
                 :: "r"(saddr), "l"(__cvta_generic_to_global(gptr)) : "memory");
}
__device__ __forceinline__ void cp_commit() {
    asm volatile("cp.async.commit_group;" ::: "memory");
}
__device__ __forceinline__ void cp_wait0() {
    asm volatile("cp.async.wait_group 0;" ::: "memory");
}
__device__ __forceinline__ void cp_wait1() {
    asm volatile("cp.async.wait_group 1;" ::: "memory");
}
__device__ __forceinline__ void ldmx4(uint32_t* r, uint32_t addr) {
    asm volatile("ldmatrix.sync.aligned.m8n8.x4.shared.b16 {%0,%1,%2,%3}, [%4];"
                 : "=r"(r[0]), "=r"(r[1]), "=r"(r[2]), "=r"(r[3]) : "r"(addr));
}
__device__ __forceinline__ void mma16816(float* d, const uint32_t* a, uint32_t b0, uint32_t b1) {
    asm volatile("mma.sync.aligned.m16n8k16.row.col.f32.f16.f16.f32 "
                 "{%0,%1,%2,%3}, {%4,%5,%6,%7}, {%8,%9}, {%0,%1,%2,%3};"
                 : "+f"(d[0]), "+f"(d[1]), "+f"(d[2]), "+f"(d[3])
                 : "r"(a[0]), "r"(a[1]), "r"(a[2]), "r"(a[3]), "r"(b0), "r"(b1));
}

// ---------------------------------------------------------------- prep: x -> fp16 transposed [d][j]
__global__ void prep_xT_kernel(const float* __restrict__ x) {
    __shared__ float tile[32][33];
    const int j0 = blockIdx.x * 32;
    const int d0 = blockIdx.y * 32;
    const int tx = threadIdx.x, ty = threadIdx.y;   // 32 x 8
#pragma unroll
    for (int k = 0; k < 32; k += 8)
        tile[ty + k][tx] = x[(size_t)(j0 + ty + k) * DCOLS + d0 + tx];
    __syncthreads();
#pragma unroll
    for (int k = 0; k < 32; k += 8)
        g_xT[(size_t)(d0 + ty + k) * NROWS + j0 + tx] = __float2half_rn(tile[tx][ty + k]);
}

// ---------------------------------------------------------------- main GEMM
__global__ void __launch_bounds__(256, 1) adjmm_kernel(
    const float* __restrict__ x, const int* __restrict__ adj, float* __restrict__ out)
{
    extern __shared__ char smraw[];
    char* sm = (char*)((((uintptr_t)smraw) + 1023) & ~(uintptr_t)1023);
    const uint32_t sb = smem_u32(sm);
    const uint32_t A_BUF[2] = { sb,           sb + 16384 };
    const uint32_t B_BUF[2] = { sb + 32768,   sb + 49152 };

    const int tid  = threadIdx.x;
    const int w    = tid >> 5;
    const int lane = tid & 31;
    const int wr   = w >> 1;          // warp row (0..3) -> m offset 32*wr
    const int wc   = w & 1;           // warp col (0..1) -> n offset 64*wc
    const int m0g  = blockIdx.x * TILE_M;

    // ---- staged A registers (raw int32 0/1, converted at STS time)
    int4 ra[8];

    auto ldgA = [&](int c) {
#pragma unroll
        for (int i = 0; i < 8; ++i) {
            int idx = i * 256 + tid;            // 0..2047 -> 128 rows x 16 int4
            int row = idx >> 4, q = idx & 15;
            ra[i] = *(const int4*)(adj + (size_t)(m0g + row) * NROWS + c * TILE_K + q * 4);
        }
    };
    auto stsA = [&](uint32_t base) {
#pragma unroll
        for (int i = 0; i < 8; ++i) {
            int idx = i * 256 + tid;
            int row = idx >> 4, q = idx & 15;
            uint32_t p01 = __byte_perm((uint32_t)ra[i].x, (uint32_t)ra[i].y, 0x5410) * 0x3C00u;
            uint32_t p23 = __byte_perm((uint32_t)ra[i].z, (uint32_t)ra[i].w, 0x5410) * 0x3C00u;
            sts64(base + sw128((uint32_t)(row * 128 + q * 8)), p01, p23);
        }
    };
    auto cpB = [&](int c, uint32_t base) {
#pragma unroll
        for (int i = 0; i < 4; ++i) {
            int idx = i * 256 + tid;            // 0..1023 -> 128 rows x 8 segs
            int row = idx >> 3, seg = idx & 7;
            cp_async16(base + sw128((uint32_t)(row * 128 + seg * 16)),
                       g_xT + (size_t)row * NROWS + c * TILE_K + seg * 8);
        }
        cp_commit();
    };

    float acc[2][8][4];
#pragma unroll
    for (int mf = 0; mf < 2; ++mf)
#pragma unroll
        for (int nf = 0; nf < 8; ++nf)
#pragma unroll
            for (int i = 0; i < 4; ++i) acc[mf][nf][i] = 0.0f;

    // ---- prologue
    ldgA(0);
    stsA(A_BUF[0]);
    ldgA(1);
    cpB(0, B_BUF[0]);
    cpB(1, B_BUF[1]);
    cp_wait1();           // B0 landed
    __syncthreads();      // A0 + B0 visible

    // ---- main loop: compute(c) | STS A(c+1) | LDG A(c+2) | cp.async B(c+2)
    for (int c = 0; c < CHUNKS; ++c) {
        const int s = c & 1;
        const uint32_t Ab = A_BUF[s], Bb = B_BUF[s];

        // A fragments for the whole chunk: 2 m-frags x 4 k-steps
        uint32_t af[2][4][4];
#pragma unroll
        for (int mf = 0; mf < 2; ++mf)
#pragma unroll
            for (int ks = 0; ks < 4; ++ks) {
                uint32_t row = (uint32_t)(wr * 32 + mf * 16 + (lane & 15));
                uint32_t off = sw128(row * 128 + ks * 32 + ((lane >> 4) << 4));
                ldmx4(af[mf][ks], Ab + off);
            }

#pragma unroll
        for (int nf = 0; nf < 8; ++nf) {
#pragma unroll
            for (int h = 0; h < 2; ++h) {       // k half-chunks of 32
                uint32_t bf[4];
                uint32_t row = (uint32_t)(wc * 64 + nf * 8 + (lane & 7));
                uint32_t off = sw128(row * 128 + h * 64 + ((lane >> 3) << 4));
                ldmx4(bf, Bb + off);
#pragma unroll
                for (int ksl = 0; ksl < 2; ++ksl) {
                    const int ks = h * 2 + ksl;
                    mma16816(acc[0][nf], af[0][ks], bf[2 * ksl], bf[2 * ksl + 1]);
                    mma16816(acc[1][nf], af[1][ks], bf[2 * ksl], bf[2 * ksl + 1]);
                }
            }
        }

        if (c + 1 < CHUNKS) stsA(A_BUF[s ^ 1]);     // A(c+1), regs loaded last iter
        if (c + 2 < CHUNKS) ldgA(c + 2);            // prefetch into regs
        cp_wait0();                                 // B(c+1) landed
        __syncthreads();                            // everyone done with buf s
        if (c + 2 < CHUNKS) cpB(c + 2, B_BUF[s]);   // refill freed buffer
    }

    // ---- epilogue: out = x + acc
#pragma unroll
    for (int mf = 0; mf < 2; ++mf) {
#pragma unroll
        for (int nf = 0; nf < 8; ++nf) {
            const int m = m0g + wr * 32 + mf * 16 + (lane >> 2);
            const int n = wc * 64 + nf * 8 + (lane & 3) * 2;
            float2 xv0 = *(const float2*)(x + (size_t)m * DCOLS + n);
            float2 o0  = { acc[mf][nf][0] + xv0.x, acc[mf][nf][1] + xv0.y };
            *(float2*)(out + (size_t)m * DCOLS + n) = o0;
            float2 xv1 = *(const float2*)(x + (size_t)(m + 8) * DCOLS + n);
            float2 o1  = { acc[mf][nf][2] + xv1.x, acc[mf][nf][3] + xv1.y };
            *(float2*)(out + (size_t)(m + 8) * DCOLS + n) = o1;
        }
    }
}

// ---------------------------------------------------------------- launcher
extern "C" void kernel_launch(void* const* d_in, const int* in_sizes, int n_in,
                              void* d_out, int out_size) {
    const float* x   = (const float*)d_in[0];
    const int*   adj = (const int*)d_in[1];
    float*       out = (float*)d_out;
    (void)in_sizes; (void)n_in; (void)out_size;

    prep_xT_kernel<<<dim3(NROWS / 32, DCOLS / 32), dim3(32, 8)>>>(x);

    cudaFuncSetAttribute(adjmm_kernel, cudaFuncAttributeMaxDynamicSharedMemorySize, SMEM_DYN);
    adjmm_kernel<<<NROWS / TILE_M, 256, SMEM_DYN>>>(x, adj, out);
}